// round 1
// baseline (speedup 1.0000x reference)
#include <cuda_runtime.h>
#include <cstdint>

#define N_USERS 40000
#define N_ITEMS 60000
#define N_NODES 100000
#define N_EDGES 1280000
#define EMB 64
#define NEG_SLOPE 0.2f

// Scratch: current embeddings e, spmm result x. 25.6 MB each.
__device__ float g_e[N_NODES * EMB];
__device__ float g_x[N_NODES * EMB];

// ---------------------------------------------------------------------------
// init: e = concat(user_emb, item_emb); acc (d_out) = e
// ---------------------------------------------------------------------------
__global__ void k_init(const float* __restrict__ ue, const float* __restrict__ ie,
                       float* __restrict__ out) {
    int i = blockIdx.x * blockDim.x + threadIdx.x;   // float4 index
    const int total4 = N_NODES * EMB / 4;
    if (i >= total4) return;
    const int user4 = N_USERS * EMB / 4;
    float4 v;
    if (i < user4) v = ((const float4*)ue)[i];
    else           v = ((const float4*)ie)[i - user4];
    ((float4*)g_e)[i] = v;
    ((float4*)out)[i] = v;
}

// ---------------------------------------------------------------------------
// zero x
// ---------------------------------------------------------------------------
__global__ void k_zero() {
    int i = blockIdx.x * blockDim.x + threadIdx.x;
    const int total4 = N_NODES * EMB / 4;
    if (i >= total4) return;
    ((float4*)g_x)[i] = make_float4(0.f, 0.f, 0.f, 0.f);
}

// ---------------------------------------------------------------------------
// SpMM: x[row] += val * e[col]   (16 threads per edge, float4 chunks,
// vector reduction red.global.add.v4.f32 — sm_90+)
// ---------------------------------------------------------------------------
__global__ void k_spmm(const int* __restrict__ erow, const int* __restrict__ ecol,
                       const float* __restrict__ eval) {
    long long t = (long long)blockIdx.x * blockDim.x + threadIdx.x;
    if (t >= (long long)N_EDGES * 16) return;
    int e = (int)(t >> 4);
    int c = (int)(t & 15);
    int r  = erow[e];
    int cl = ecol[e];
    float v = eval[e];
    float4 f = ((const float4*)g_e)[cl * 16 + c];
    float4 m = make_float4(v * f.x, v * f.y, v * f.z, v * f.w);
    float* p = g_x + (size_t)r * EMB + c * 4;
    asm volatile("red.global.add.v4.f32 [%0], {%1, %2, %3, %4};"
                 :: "l"(p), "f"(m.x), "f"(m.y), "f"(m.z), "f"(m.w)
                 : "memory");
}

// ---------------------------------------------------------------------------
// Dense layer: h = (e+x)@W1 + (x*e)@W2 + b1 + b2 ; leaky-relu ; l2norm ->
//   e_new ; out = (out + e_new) * scale
//
// Block: 64 nodes x 64 cols, 256 threads (16x16), each thread 4 nodes x 4 cols.
// K=128 split into 2 phases of 64 (phase0: u=e+x with W1, phase1: v=x*e with W2)
// so the shared W tile can be reused (keeps static smem under 48KB).
// ---------------------------------------------------------------------------
__global__ void __launch_bounds__(256) k_dense(
    const float* __restrict__ W1, const float* __restrict__ b1,
    const float* __restrict__ W2, const float* __restrict__ b2,
    float* __restrict__ out, float scale) {

    __shared__ float sW[64][64];     // 16 KB
    __shared__ float sUV[64][67];    // 17.2 KB (pad 67 -> mild conflicts only)

    const int tid = threadIdx.x;
    const int tx = tid & 15;         // col group: cols tx*4 .. tx*4+3
    const int ty = tid >> 4;         // node group: nodes ty*4 .. ty*4+3
    const int base = blockIdx.x * 64;

    float acc[4][4];
    #pragma unroll
    for (int a = 0; a < 4; a++)
        #pragma unroll
        for (int j = 0; j < 4; j++) acc[a][j] = 0.f;

    #pragma unroll
    for (int ph = 0; ph < 2; ph++) {
        if (ph) __syncthreads();     // phase-0 reads finished before overwrite
        const float* W = ph ? W2 : W1;

        // load W tile: 64x64 floats = 1024 float4, 256 threads -> 4 each
        #pragma unroll
        for (int it = 0; it < 4; it++) {
            int i = tid + it * 256;
            ((float4*)&sW[0][0])[i] = ((const float4*)W)[i];
        }

        // build UV tile transposed: sUV[k][node_local]
        #pragma unroll
        for (int it = 0; it < 4; it++) {
            int i = tid + it * 256;          // 0..1023
            int nd = i >> 4;                 // local node 0..63
            int c4 = i & 15;                 // float4 chunk 0..15
            int node = base + nd;
            float4 ev = make_float4(0.f, 0.f, 0.f, 0.f);
            float4 xv = make_float4(0.f, 0.f, 0.f, 0.f);
            if (node < N_NODES) {
                ev = ((const float4*)g_e)[node * 16 + c4];
                xv = ((const float4*)g_x)[node * 16 + c4];
            }
            float4 u;
            if (ph == 0) {
                u = make_float4(ev.x + xv.x, ev.y + xv.y, ev.z + xv.z, ev.w + xv.w);
            } else {
                u = make_float4(ev.x * xv.x, ev.y * xv.y, ev.z * xv.z, ev.w * xv.w);
            }
            sUV[c4 * 4 + 0][nd] = u.x;
            sUV[c4 * 4 + 1][nd] = u.y;
            sUV[c4 * 4 + 2][nd] = u.z;
            sUV[c4 * 4 + 3][nd] = u.w;
        }
        __syncthreads();

        #pragma unroll 16
        for (int k = 0; k < 64; k++) {
            float4 w = *(const float4*)&sW[k][tx * 4];
            float u0 = sUV[k][ty * 4 + 0];
            float u1 = sUV[k][ty * 4 + 1];
            float u2 = sUV[k][ty * 4 + 2];
            float u3 = sUV[k][ty * 4 + 3];
            acc[0][0] += u0 * w.x; acc[0][1] += u0 * w.y; acc[0][2] += u0 * w.z; acc[0][3] += u0 * w.w;
            acc[1][0] += u1 * w.x; acc[1][1] += u1 * w.y; acc[1][2] += u1 * w.z; acc[1][3] += u1 * w.w;
            acc[2][0] += u2 * w.x; acc[2][1] += u2 * w.y; acc[2][2] += u2 * w.z; acc[2][3] += u2 * w.w;
            acc[3][0] += u3 * w.x; acc[3][1] += u3 * w.y; acc[3][2] += u3 * w.z; acc[3][3] += u3 * w.w;
        }
    }

    // epilogue: bias, leaky relu, l2 normalize, write e, accumulate out
    const int j0 = tx * 4;
    float bb0 = b1[j0 + 0] + b2[j0 + 0];
    float bb1 = b1[j0 + 1] + b2[j0 + 1];
    float bb2 = b1[j0 + 2] + b2[j0 + 2];
    float bb3 = b1[j0 + 3] + b2[j0 + 3];

    #pragma unroll
    for (int a = 0; a < 4; a++) {
        float h0 = acc[a][0] + bb0;
        float h1 = acc[a][1] + bb1;
        float h2 = acc[a][2] + bb2;
        float h3 = acc[a][3] + bb3;
        h0 = (h0 >= 0.f) ? h0 : NEG_SLOPE * h0;
        h1 = (h1 >= 0.f) ? h1 : NEG_SLOPE * h1;
        h2 = (h2 >= 0.f) ? h2 : NEG_SLOPE * h2;
        h3 = (h3 >= 0.f) ? h3 : NEG_SLOPE * h3;
        float ss = h0 * h0 + h1 * h1 + h2 * h2 + h3 * h3;
        // reduce across the 16 lanes that share this node (lanes differ in low 4 bits)
        ss += __shfl_xor_sync(0xffffffffu, ss, 1);
        ss += __shfl_xor_sync(0xffffffffu, ss, 2);
        ss += __shfl_xor_sync(0xffffffffu, ss, 4);
        ss += __shfl_xor_sync(0xffffffffu, ss, 8);
        float inv = rsqrtf(fmaxf(ss, 1e-24f));
        float e0 = h0 * inv, e1 = h1 * inv, e2 = h2 * inv, e3 = h3 * inv;

        int node = base + ty * 4 + a;
        if (node < N_NODES) {
            ((float4*)g_e)[node * 16 + tx] = make_float4(e0, e1, e2, e3);
            float4 o = ((float4*)out)[node * 16 + tx];
            o.x = (o.x + e0) * scale;
            o.y = (o.y + e1) * scale;
            o.z = (o.z + e2) * scale;
            o.w = (o.w + e3) * scale;
            ((float4*)out)[node * 16 + tx] = o;
        }
    }
}

// ---------------------------------------------------------------------------
extern "C" void kernel_launch(void* const* d_in, const int* in_sizes, int n_in,
                              void* d_out, int out_size) {
    const int*   erow = (const int*)d_in[0];
    const int*   ecol = (const int*)d_in[1];
    const float* eval = (const float*)d_in[2];
    const float* ue   = (const float*)d_in[3];
    const float* ie   = (const float*)d_in[4];
    const float* W1   = (const float*)d_in[5];
    const float* b1   = (const float*)d_in[6];
    const float* W2   = (const float*)d_in[7];
    const float* b2   = (const float*)d_in[8];
    float* out = (float*)d_out;

    const int total4 = N_NODES * EMB / 4;                 // 1.6M
    const int init_blocks = (total4 + 255) / 256;         // 6250
    const long long spmm_threads = (long long)N_EDGES * 16;
    const int spmm_blocks = (int)((spmm_threads + 255) / 256);  // 80000
    const int dense_blocks = (N_NODES + 63) / 64;         // 1563

    k_init<<<init_blocks, 256>>>(ue, ie, out);
    for (int l = 0; l < 3; l++) {
        k_zero<<<init_blocks, 256>>>();
        k_spmm<<<spmm_blocks, 256>>>(erow, ecol, eval);
        float scale = (l == 2) ? 0.25f : 1.0f;
        k_dense<<<dense_blocks, 256>>>(W1 + l * EMB * EMB, b1 + l * EMB,
                                       W2 + l * EMB * EMB, b2 + l * EMB,
                                       out, scale);
    }
}